// round 1
// baseline (speedup 1.0000x reference)
#include <cuda_runtime.h>
#include <math.h>

#define W_ 256
#define H_ 256
#define NMAX 1024
#define NFIELD 13
// field layout: 0 mx, 1 my, 2 0.5*conicA, 3 conicB, 4 0.5*conicC,
//               5 opac, 6 r, 7 g, 8 b, 9 x0, 10 x1, 11 y0, 12 y1

__device__ float g_tmp[NFIELD][NMAX];
__device__ float g_tz[NMAX];
__device__ float g_sorted[NFIELD][NMAX];

__global__ void gs_preprocess(const float* __restrict__ means,
                              const float* __restrict__ quats,
                              const float* __restrict__ scales,
                              const float* __restrict__ opac_in,
                              const float* __restrict__ rgbs,
                              int n) {
    int i = blockIdx.x * blockDim.x + threadIdx.x;
    if (i >= n) return;

    // normalize quaternion
    float qw = quats[i*4+0], qx = quats[i*4+1], qy = quats[i*4+2], qz = quats[i*4+3];
    float inv = 1.0f / sqrtf(qw*qw + qx*qx + qy*qy + qz*qz);
    float w = qw*inv, x = qx*inv, y = qy*inv, z = qz*inv;

    float R00 = 1.f - 2.f*(y*y + z*z), R01 = 2.f*(x*y - w*z), R02 = 2.f*(x*z + w*y);
    float R10 = 2.f*(x*y + w*z), R11 = 1.f - 2.f*(x*x + z*z), R12 = 2.f*(y*z - w*x);
    float R20 = 2.f*(x*z - w*y), R21 = 2.f*(y*z + w*x), R22 = 1.f - 2.f*(x*x + y*y);

    float sx = scales[i*3+0], sy = scales[i*3+1], sz = scales[i*3+2];
    float s0 = sx*sx, s1 = sy*sy, s2 = sz*sz;

    // cov3d = R diag(s^2) R^T
    float C00 = R00*R00*s0 + R01*R01*s1 + R02*R02*s2;
    float C01 = R00*R10*s0 + R01*R11*s1 + R02*R12*s2;
    float C02 = R00*R20*s0 + R01*R21*s1 + R02*R22*s2;
    float C11 = R10*R10*s0 + R11*R11*s1 + R12*R12*s2;
    float C12 = R10*R20*s0 + R11*R21*s1 + R12*R22*s2;
    float C22 = R20*R20*s0 + R21*R21*s1 + R22*R22*s2;

    float tx = means[i*3+0], ty = means[i*3+1], tz = means[i*3+2] + 8.0f;
    const float f = 128.0f;
    float iz = 1.0f / tz;
    float j00 = f * iz;                 // == j11
    float j02 = -f * tx * iz * iz;
    float j12 = -f * ty * iz * iz;

    // cov2d = J cov3d J^T + eps*I
    float a = j00*j00*C00 + 2.f*j00*j02*C02 + j02*j02*C22 + 0.3f;
    float b = j00*j00*C01 + j00*j12*C02 + j02*j00*C12 + j02*j12*C22;
    float c = j00*j00*C11 + 2.f*j00*j12*C12 + j12*j12*C22 + 0.3f;

    float det = a*c - b*b;
    float idet = 1.0f / det;
    float cA = c * idet, cB = -b * idet, cC = a * idet;

    float mx = f * tx * iz + 128.0f;
    float my = f * ty * iz + 128.0f;

    float op = 1.0f / (1.0f + __expf(-opac_in[i]));
    float cr = 1.0f / (1.0f + __expf(-rgbs[i*3+0]));
    float cg = 1.0f / (1.0f + __expf(-rgbs[i*3+1]));
    float cb = 1.0f / (1.0f + __expf(-rgbs[i*3+2]));

    // bounding box from ALPHA_MIN cutoff: sigma <= log(255*opac).
    // dx_max = sqrt(2*t*cov2d_a), dy_max = sqrt(2*t*cov2d_c); pad 0.5px.
    float tcut = __logf(op * 255.0f);
    float ex, ey;
    if (tcut > 0.0f) {
        ex = sqrtf(2.0f * tcut * a) + 0.5f;
        ey = sqrtf(2.0f * tcut * c) + 0.5f;
    } else {
        ex = -1e30f; ey = -1e30f;  // empty box -> never intersects any tile
    }

    g_tmp[0][i]  = mx;
    g_tmp[1][i]  = my;
    g_tmp[2][i]  = 0.5f * cA;
    g_tmp[3][i]  = cB;
    g_tmp[4][i]  = 0.5f * cC;
    g_tmp[5][i]  = op;
    g_tmp[6][i]  = cr;
    g_tmp[7][i]  = cg;
    g_tmp[8][i]  = cb;
    g_tmp[9][i]  = mx - ex;
    g_tmp[10][i] = mx + ex;
    g_tmp[11][i] = my - ey;
    g_tmp[12][i] = my + ey;
    g_tz[i] = tz;
}

// One warp per gaussian: O(N) comparisons per warp -> rank -> scatter 13 fields.
// Stable ascending rank matches jnp.argsort(tz).
__global__ void gs_sort_scatter(int n) {
    int gwarp = (blockIdx.x * blockDim.x + threadIdx.x) >> 5;
    int lane  = threadIdx.x & 31;
    if (gwarp >= n) return;

    float ti = g_tz[gwarp];
    int rank = 0;
    for (int j = lane; j < n; j += 32) {
        float tj = g_tz[j];
        rank += (tj < ti || (tj == ti && j < gwarp)) ? 1 : 0;
    }
    #pragma unroll
    for (int off = 16; off > 0; off >>= 1)
        rank += __shfl_down_sync(0xffffffffu, rank, off);
    rank = __shfl_sync(0xffffffffu, rank, 0);

    if (lane < NFIELD)
        g_sorted[lane][rank] = g_tmp[lane][gwarp];
}

__global__ __launch_bounds__(256) void gs_render(float* __restrict__ out, int n) {
    __shared__ unsigned short s_idx[NMAX];
    __shared__ float s_mx[NMAX], s_my[NMAX];
    __shared__ float s_ca[NMAX], s_cb[NMAX], s_cc[NMAX];
    __shared__ float s_op[NMAX];
    __shared__ float s_r[NMAX], s_g[NMAX], s_b[NMAX];
    __shared__ int s_cnt;

    const int tx = threadIdx.x, ty = threadIdx.y;
    const int tid = ty * 16 + tx;
    const int px0 = blockIdx.x * 16, py0 = blockIdx.y * 16;

    // tile pixel-center bounds
    const float tlx = px0 + 0.5f,  thx = px0 + 15.5f;
    const float tly = py0 + 0.5f,  thy = py0 + 15.5f;

    // warp 0: order-preserving compaction of gaussians intersecting this tile
    if (tid < 32) {
        int cnt = 0;
        for (int base = 0; base < n; base += 32) {
            int g = base + tid;
            bool pred = false;
            if (g < n) {
                pred = (g_sorted[10][g] >= tlx) & (g_sorted[9][g]  <= thx) &
                       (g_sorted[12][g] >= tly) & (g_sorted[11][g] <= thy);
            }
            unsigned m = __ballot_sync(0xffffffffu, pred);
            if (pred)
                s_idx[cnt + __popc(m & ((1u << tid) - 1u))] = (unsigned short)g;
            cnt += __popc(m);
        }
        if (tid == 0) s_cnt = cnt;
    }
    __syncthreads();
    const int cnt = s_cnt;

    // stage compacted gaussian data into shared (whole block)
    for (int k = tid; k < cnt; k += 256) {
        int g = s_idx[k];
        s_mx[k] = g_sorted[0][g];
        s_my[k] = g_sorted[1][g];
        s_ca[k] = g_sorted[2][g];
        s_cb[k] = g_sorted[3][g];
        s_cc[k] = g_sorted[4][g];
        s_op[k] = g_sorted[5][g];
        s_r[k]  = g_sorted[6][g];
        s_g[k]  = g_sorted[7][g];
        s_b[k]  = g_sorted[8][g];
    }
    __syncthreads();

    const float pxc = px0 + tx + 0.5f;
    const float pyc = py0 + ty + 0.5f;

    float T = 1.0f, accr = 0.0f, accg = 0.0f, accb = 0.0f;
    for (int k = 0; k < cnt; k++) {
        float dx = pxc - s_mx[k];
        float dy = pyc - s_my[k];
        float sigma = s_ca[k]*dx*dx + s_cc[k]*dy*dy + s_cb[k]*dx*dy;
        float alpha = fminf(0.999f, s_op[k] * __expf(-sigma));
        if (alpha >= (1.0f / 255.0f)) {
            float wgt = T * alpha;
            accr += wgt * s_r[k];
            accg += wgt * s_g[k];
            accb += wgt * s_b[k];
            T *= (1.0f - alpha);
            if (T < 2e-6f) break;   // remaining contribution < 2e-6 absolute
        }
    }

    int p = (py0 + ty) * W_ + (px0 + tx);
    out[3*p + 0] = accr;
    out[3*p + 1] = accg;
    out[3*p + 2] = accb;
}

extern "C" void kernel_launch(void* const* d_in, const int* in_sizes, int n_in,
                              void* d_out, int out_size) {
    // inputs: 0 coords (unused), 1 means, 2 quats, 3 scales, 4 opacities, 5 rgbs
    const float* means  = (const float*)d_in[1];
    const float* quats  = (const float*)d_in[2];
    const float* scales = (const float*)d_in[3];
    const float* opac   = (const float*)d_in[4];
    const float* rgbs   = (const float*)d_in[5];
    int n = in_sizes[4];

    gs_preprocess<<<(n + 255) / 256, 256>>>(means, quats, scales, opac, rgbs, n);
    gs_sort_scatter<<<(n * 32 + 255) / 256, 256>>>(n);
    dim3 grid(W_ / 16, H_ / 16), block(16, 16);
    gs_render<<<grid, block>>>((float*)d_out, n);
}

// round 2
// speedup vs baseline: 1.1067x; 1.1067x over previous
#include <cuda_runtime.h>
#include <math.h>

#define W_ 256
#define H_ 256
#define NMAX 768
#define CUT_SIGMA 5.5412636f   // log(255): alpha >= 1/255  <=>  sigma <= log(255)

// unsorted (preprocess output)
__device__ float4 g_A0[NMAX];     // mx, my, 0.5*conicA, 0.5*conicC
__device__ float4 g_B0[NMAX];     // conicB, bias(=-log op), r, g
__device__ float  g_bv0[NMAX];    // blue
__device__ float4 g_bb0[NMAX];    // x0, x1, y0, y1
__device__ float  g_tz[NMAX];
// depth-sorted
__device__ float4 g_A[NMAX];
__device__ float4 g_B[NMAX];
__device__ float  g_bv[NMAX];
__device__ float4 g_bb[NMAX];

__global__ void gs_preprocess(const float* __restrict__ means,
                              const float* __restrict__ quats,
                              const float* __restrict__ scales,
                              const float* __restrict__ opac_in,
                              const float* __restrict__ rgbs,
                              int n) {
    int i = blockIdx.x * blockDim.x + threadIdx.x;
    if (i >= n) return;

    float qw = quats[i*4+0], qx = quats[i*4+1], qy = quats[i*4+2], qz = quats[i*4+3];
    float inv = rsqrtf(qw*qw + qx*qx + qy*qy + qz*qz);
    float w = qw*inv, x = qx*inv, y = qy*inv, z = qz*inv;

    float R00 = 1.f - 2.f*(y*y + z*z), R01 = 2.f*(x*y - w*z), R02 = 2.f*(x*z + w*y);
    float R10 = 2.f*(x*y + w*z), R11 = 1.f - 2.f*(x*x + z*z), R12 = 2.f*(y*z - w*x);
    float R20 = 2.f*(x*z - w*y), R21 = 2.f*(y*z + w*x), R22 = 1.f - 2.f*(x*x + y*y);

    float sx = scales[i*3+0], sy = scales[i*3+1], sz = scales[i*3+2];
    float s0 = sx*sx, s1 = sy*sy, s2 = sz*sz;

    float C00 = R00*R00*s0 + R01*R01*s1 + R02*R02*s2;
    float C01 = R00*R10*s0 + R01*R11*s1 + R02*R12*s2;
    float C02 = R00*R20*s0 + R01*R21*s1 + R02*R22*s2;
    float C11 = R10*R10*s0 + R11*R11*s1 + R12*R12*s2;
    float C12 = R10*R20*s0 + R11*R21*s1 + R12*R22*s2;
    float C22 = R20*R20*s0 + R21*R21*s1 + R22*R22*s2;

    float tx = means[i*3+0], ty = means[i*3+1], tz = means[i*3+2] + 8.0f;
    const float f = 128.0f;
    float iz = 1.0f / tz;
    float j00 = f * iz;
    float j02 = -f * tx * iz * iz;
    float j12 = -f * ty * iz * iz;

    float a = j00*j00*C00 + 2.f*j00*j02*C02 + j02*j02*C22 + 0.3f;
    float b = j00*j00*C01 + j00*j12*C02 + j02*j00*C12 + j02*j12*C22;
    float c = j00*j00*C11 + 2.f*j00*j12*C12 + j12*j12*C22 + 0.3f;

    float det = a*c - b*b;
    float idet = 1.0f / det;
    float cA = c * idet, cB = -b * idet, cC = a * idet;

    float mx = f * tx * iz + 128.0f;
    float my = f * ty * iz + 128.0f;

    float op = 1.0f / (1.0f + __expf(-opac_in[i]));
    float cr = 1.0f / (1.0f + __expf(-rgbs[i*3+0]));
    float cg = 1.0f / (1.0f + __expf(-rgbs[i*3+1]));
    float cb = 1.0f / (1.0f + __expf(-rgbs[i*3+2]));

    float bias = -__logf(op);             // sigma' = quad + bias; alpha = exp(-sigma')
    float tcut = CUT_SIGMA - bias;        // log(255*op)
    float ex, ey;
    if (tcut > 0.0f) {
        ex = sqrtf(2.0f * tcut * a) + 0.5f;
        ey = sqrtf(2.0f * tcut * c) + 0.5f;
    } else {
        ex = -1e30f; ey = -1e30f;
    }

    g_A0[i]  = make_float4(mx, my, 0.5f * cA, 0.5f * cC);
    g_B0[i]  = make_float4(cB, bias, cr, cg);
    g_bv0[i] = cb;
    g_bb0[i] = make_float4(mx - ex, mx + ex, my - ey, my + ey);
    g_tz[i]  = tz;
}

// thread-per-gaussian stable rank sort + scatter
__global__ void gs_sort_scatter(int n) {
    int i = blockIdx.x * blockDim.x + threadIdx.x;
    if (i >= n) return;
    float ti = g_tz[i];
    int rank = 0;
    #pragma unroll 4
    for (int j = 0; j < n; j++) {
        float tj = g_tz[j];
        rank += (tj < ti || (tj == ti && j < i)) ? 1 : 0;
    }
    g_A[rank]  = g_A0[i];
    g_B[rank]  = g_B0[i];
    g_bv[rank] = g_bv0[i];
    g_bb[rank] = g_bb0[i];
}

__global__ __launch_bounds__(256) void gs_render(float* __restrict__ out, int n) {
    __shared__ float4 sA[NMAX];
    __shared__ float4 sB[NMAX];
    __shared__ float  sBV[NMAX];
    __shared__ unsigned short s_idx[NMAX];
    __shared__ int s_wcnt[8];
    __shared__ int s_woff[8];
    __shared__ int s_cnt;

    const int tx = threadIdx.x, ty = threadIdx.y;
    const int tid = ty * 16 + tx;
    const int warp = tid >> 5, lane = tid & 31;
    const int px0 = blockIdx.x * 16, py0 = blockIdx.y * 16;

    const float tlx = px0 + 0.5f,  thx = px0 + 15.5f;
    const float tly = py0 + 0.5f,  thy = py0 + 15.5f;

    // parallel order-preserving compaction: 8 warps, each over a contiguous chunk
    const int nIter = (n + 255) / 256;        // 32-elem groups per warp
    const int beg = warp * nIter * 32;
    int cnt = 0;
    for (int it = 0; it < nIter; it++) {
        int g = beg + it * 32 + lane;
        bool pred = false;
        if (g < n) {
            float4 bb = g_bb[g];
            pred = (bb.y >= tlx) & (bb.x <= thx) & (bb.w >= tly) & (bb.z <= thy);
        }
        unsigned m = __ballot_sync(0xffffffffu, pred);
        cnt += __popc(m);
    }
    if (lane == 0) s_wcnt[warp] = cnt;
    __syncthreads();
    if (tid == 0) {
        int o = 0;
        #pragma unroll
        for (int w = 0; w < 8; w++) { s_woff[w] = o; o += s_wcnt[w]; }
        s_cnt = o;
    }
    __syncthreads();
    int off = s_woff[warp];
    for (int it = 0; it < nIter; it++) {
        int g = beg + it * 32 + lane;
        bool pred = false;
        if (g < n) {
            float4 bb = g_bb[g];
            pred = (bb.y >= tlx) & (bb.x <= thx) & (bb.w >= tly) & (bb.z <= thy);
        }
        unsigned m = __ballot_sync(0xffffffffu, pred);
        if (pred)
            s_idx[off + __popc(m & ((1u << lane) - 1u))] = (unsigned short)g;
        off += __popc(m);
    }
    __syncthreads();
    const int tcnt = s_cnt;

    // stage compacted gaussians into shared
    for (int k = tid; k < tcnt; k += 256) {
        int g = s_idx[k];
        sA[k]  = g_A[g];
        sB[k]  = g_B[g];
        sBV[k] = g_bv[g];
    }
    __syncthreads();

    const float pxc = px0 + tx + 0.5f;
    const float pyc = py0 + ty + 0.5f;

    float T = 1.0f, accr = 0.0f, accg = 0.0f, accb = 0.0f;
    #pragma unroll 2
    for (int k = 0; k < tcnt; k++) {
        float4 A = sA[k];
        float dx = pxc - A.x;
        float dy = pyc - A.y;
        float4 B = sB[k];
        float sigma = fmaf(A.z, dx*dx, fmaf(A.w, dy*dy, fmaf(B.x, dx*dy, B.y)));
        if (sigma <= CUT_SIGMA) {
            float alpha = fminf(0.999f, __expf(-sigma));
            float wgt = T * alpha;
            accr = fmaf(wgt, B.z, accr);
            accg = fmaf(wgt, B.w, accg);
            accb = fmaf(wgt, sBV[k], accb);
            T -= T * alpha;
            if (T < 2e-6f) break;
        }
    }

    int p = (py0 + ty) * W_ + (px0 + tx);
    out[3*p + 0] = accr;
    out[3*p + 1] = accg;
    out[3*p + 2] = accb;
}

extern "C" void kernel_launch(void* const* d_in, const int* in_sizes, int n_in,
                              void* d_out, int out_size) {
    const float* means  = (const float*)d_in[1];
    const float* quats  = (const float*)d_in[2];
    const float* scales = (const float*)d_in[3];
    const float* opac   = (const float*)d_in[4];
    const float* rgbs   = (const float*)d_in[5];
    int n = in_sizes[4];
    if (n > NMAX) n = NMAX;

    gs_preprocess<<<(n + 255) / 256, 256>>>(means, quats, scales, opac, rgbs, n);
    gs_sort_scatter<<<(n + 255) / 256, 256>>>(n);
    dim3 grid(W_ / 16, H_ / 16), block(16, 16);
    gs_render<<<grid, block>>>((float*)d_out, n);
}